// round 15
// baseline (speedup 1.0000x reference)
#include <cuda_runtime.h>
#include <cuda_bf16.h>
#include <math.h>
#include <cstdint>

#define B_  4
#define L_  256
#define D_  256
#define P_  32
#define H_  8
#define HD_ 32
#define DH_ 128   // D/2

// ======================= mma.sync bf16 =====================================
__device__ __forceinline__ void mma16816(float* c, const unsigned* a, const unsigned* b) {
    asm volatile("mma.sync.aligned.m16n8k16.row.col.f32.bf16.bf16.f32 "
        "{%0,%1,%2,%3}, {%4,%5,%6,%7}, {%8,%9}, {%0,%1,%2,%3};"
        : "+f"(c[0]), "+f"(c[1]), "+f"(c[2]), "+f"(c[3])
        : "r"(a[0]), "r"(a[1]), "r"(a[2]), "r"(a[3]), "r"(b[0]), "r"(b[1]));
}
__device__ __forceinline__ unsigned pack_bf16x2(float x0, float x1) {
    __nv_bfloat162 t = __floats2bfloat162_rn(x0, x1);
    return *reinterpret_cast<unsigned*>(&t);
}
// fast split: hi = rn-rounded bf16 pair (1 cvt), lo from exact shift-expansion
__device__ __forceinline__ void split2(float x0, float x1, unsigned& whi, unsigned& wlo) {
    whi = pack_bf16x2(x0, x1);
    float h0 = __uint_as_float(whi << 16);
    float h1 = __uint_as_float(whi & 0xffff0000u);
    wlo = pack_bf16x2(x0 - h0, x1 - h1);
}
__device__ __forceinline__ void split1(float x, __nv_bfloat16& h, __nv_bfloat16& l) {
    h = __float2bfloat16(x);
    l = __float2bfloat16(x - __bfloat162float(h));
}

// ======================= scratch =========================================
__device__ __nv_bfloat16 g_eh[B_*L_*D_];        // ehr hi
__device__ __nv_bfloat16 g_el[B_*L_*D_];        // ehr lo
__device__ __nv_bfloat16 g_kh[B_*L_*D_];        // K single bf16
__device__ __nv_bfloat16 g_vth[B_*D_*L_];       // V^T hi [(b*D + c)][l]
__device__ __nv_bfloat16 g_vtl[B_*D_*L_];       // V^T lo
__device__ __nv_bfloat16 g_qh[B_*P_*L_*D_];     // q single bf16
__device__ __nv_bfloat16 g_ctxh[B_*P_*L_*D_];
__device__ __nv_bfloat16 g_ctxl[B_*P_*L_*D_];
__device__ __nv_bfloat16 g_hh[B_*P_*L_*DH_];
__device__ __nv_bfloat16 g_hl[B_*P_*L_*DH_];
__device__ __nv_bfloat16 g_woTh[D_*D_];         // [n][k]
__device__ __nv_bfloat16 g_woTl[D_*D_];
__device__ __nv_bfloat16 g_wkT[D_*D_];          // [n][k] single bf16
__device__ __nv_bfloat16 g_wvTh[D_*D_];         // [n][k]
__device__ __nv_bfloat16 g_wvTl[D_*D_];
__device__ __nv_bfloat16 g_w2qTh[D_*DH_];       // [n][k], scale folded
__device__ __nv_bfloat16 g_w2qTl[D_*DH_];
__device__ float g_W2q[DH_*D_];
__device__ float g_bq2[D_];                     // scale folded

// ---------------------------------------------------------------------------
// Kernel 1: W2q = w2 @ wq, bq2 = scale*(b2 @ wq + bq)
// ---------------------------------------------------------------------------
__global__ void fuse_w_kernel(const float* __restrict__ w2, const float* __restrict__ wq,
                              const float* __restrict__ b2, const float* __restrict__ bq) {
    int j = blockIdx.x, c = threadIdx.x;
    float acc = 0.f;
    for (int k = 0; k < D_; k++) acc = fmaf(w2[j*D_+k], wq[k*D_+c], acc);
    g_W2q[j*D_+c] = acc;
    if (j == 0) {
        float a = 0.f;
        for (int k = 0; k < D_; k++) a = fmaf(b2[k], wq[k*D_+c], a);
        g_bq2[c] = 0.17677669529663687f * (a + bq[c]);
    }
}

// ---------------------------------------------------------------------------
// Kernel 1b: transpose+split weights
// ---------------------------------------------------------------------------
__global__ void prep_split_kernel(const float* __restrict__ wo,
                                  const float* __restrict__ wk,
                                  const float* __restrict__ wv) {
    int n = blockIdx.x, k = threadIdx.x;
    __nv_bfloat16 h, l;
    split1(wo[k*D_ + n], h, l);
    g_woTh[n*D_ + k] = h;
    g_woTl[n*D_ + k] = l;
    g_wkT[n*D_ + k] = __float2bfloat16(wk[k*D_ + n]);
    split1(wv[k*D_ + n], h, l);
    g_wvTh[n*D_ + k] = h;
    g_wvTl[n*D_ + k] = l;
    if (k < DH_) {
        split1(0.17677669529663687f * g_W2q[k*D_ + n], h, l);
        g_w2qTh[n*DH_ + k] = h;
        g_w2qTl[n*DH_ + k] = l;
    }
}

// ---------------------------------------------------------------------------
// Kernel 1c: split ehr into hi/lo bf16
// ---------------------------------------------------------------------------
__global__ void split_ehr_kernel(const float* __restrict__ ehr) {
    int i = blockIdx.x * 256 + threadIdx.x;
    __nv_bfloat16 h, l;
    split1(ehr[i], h, l);
    g_eh[i] = h;
    g_el[i] = l;
}

// ---------------------------------------------------------------------------
// Kernel 3: time features -> MLP -> gelu -> h (split bf16)
// ---------------------------------------------------------------------------
__global__ void h_kernel(const float* __restrict__ ehr_times, const float* __restrict__ itv,
                         const float* __restrict__ w1, const float* __restrict__ b1) {
    __shared__ float3 stf[32];
    int tid = threadIdx.x;
    int g0 = blockIdx.x * 32;
    int b  = g0 / (P_*L_);
    int p  = (g0 / L_) % P_;
    int l0 = g0 % L_;
    if (tid < 32) {
        float t = ehr_times[b*L_ + l0 + tid];
        float s = itv[(b*P_+p)*2 + 0];
        float e = itv[(b*P_+p)*2 + 1];
        float ds = t - s, de = e - t;
        float x  = ds * de;
        float sg = 1.f / (1.f + expf(-x));
        stf[tid] = make_float3(ds, de, sg);
    }
    __syncthreads();
    for (int i = tid; i < 32*DH_; i += 256) {
        int r = i >> 7, j = i & 127;
        float3 tf = stf[r];
        float z = tf.x*w1[j] + tf.y*w1[DH_+j] + tf.z*w1[2*DH_+j] + b1[j];
        float v = 0.5f * z * (1.f + erff(z * 0.70710678118654752f));
        __nv_bfloat16 h, l;
        split1(v, h, l);
        g_hh[(size_t)g0*DH_ + i] = h;
        g_hl[(size_t)g0*DH_ + i] = l;
    }
}

// ---------------------------------------------------------------------------
// Generic bf16 GEMM. PROD3: hi/lo 3-product.
// OM: 0 fp32, 1 single bf16, 2 split bf16, 3 split bf16 TRANSPOSED [(b*D+n)][l]
// ---------------------------------------------------------------------------
template<int K, bool PROD3, int OM>
__global__ void __launch_bounds__(256)
gemm_kernel(const __nv_bfloat16* __restrict__ Ah, const __nv_bfloat16* __restrict__ Al,
            const __nv_bfloat16* __restrict__ BTh, const __nv_bfloat16* __restrict__ BTl,
            const float* __restrict__ bias,
            float* __restrict__ outF,
            __nv_bfloat16* __restrict__ outH, __nv_bfloat16* __restrict__ outL) {
    __shared__ __nv_bfloat16 sAh[128*40], sAl[128*40], sBh[128*40], sBl[128*40];
    int tid = threadIdx.x, wid = tid >> 5, lane = tid & 31;
    int g = lane >> 2, kq = (lane & 3) * 2;
    int wm = wid & 3, wn = wid >> 2;
    int m0 = blockIdx.x * 128, n0 = blockIdx.y * 128;

    float c[2][8][4];
#pragma unroll
    for (int nt = 0; nt < 8; nt++) {
        float2 bb = *(const float2*)&bias[n0 + wn*64 + nt*8 + kq];
#pragma unroll
        for (int mt = 0; mt < 2; mt++) {
            c[mt][nt][0] = bb.x; c[mt][nt][1] = bb.y;
            c[mt][nt][2] = bb.x; c[mt][nt][3] = bb.y;
        }
    }

    for (int kc = 0; kc < K; kc += 32) {
        for (int idx = tid; idx < 1024; idx += 256) {
            int r = idx >> 3, c4 = (idx & 7) * 4;
            *(uint2*)&sAh[r*40 + c4] = *(const uint2*)&Ah[(size_t)(m0+r)*K + kc + c4];
            *(uint2*)&sBh[r*40 + c4] = *(const uint2*)&BTh[(size_t)(n0+r)*K + kc + c4];
            if (PROD3) {
                *(uint2*)&sAl[r*40 + c4] = *(const uint2*)&Al[(size_t)(m0+r)*K + kc + c4];
                *(uint2*)&sBl[r*40 + c4] = *(const uint2*)&BTl[(size_t)(n0+r)*K + kc + c4];
            }
        }
        __syncthreads();
#pragma unroll
        for (int kt = 0; kt < 2; kt++) {
            unsigned ah[2][4], al[2][4];
#pragma unroll
            for (int mt = 0; mt < 2; mt++) {
                int rb = wm*32 + mt*16;
                ah[mt][0] = *(const unsigned*)&sAh[(rb+g  )*40 + kt*16 + kq];
                ah[mt][1] = *(const unsigned*)&sAh[(rb+g+8)*40 + kt*16 + kq];
                ah[mt][2] = *(const unsigned*)&sAh[(rb+g  )*40 + kt*16 + kq + 8];
                ah[mt][3] = *(const unsigned*)&sAh[(rb+g+8)*40 + kt*16 + kq + 8];
                if (PROD3) {
                    al[mt][0] = *(const unsigned*)&sAl[(rb+g  )*40 + kt*16 + kq];
                    al[mt][1] = *(const unsigned*)&sAl[(rb+g+8)*40 + kt*16 + kq];
                    al[mt][2] = *(const unsigned*)&sAl[(rb+g  )*40 + kt*16 + kq + 8];
                    al[mt][3] = *(const unsigned*)&sAl[(rb+g+8)*40 + kt*16 + kq + 8];
                }
            }
#pragma unroll
            for (int nt = 0; nt < 8; nt++) {
                int rn = wn*64 + nt*8 + g;
                unsigned bh[2], bl[2];
                bh[0] = *(const unsigned*)&sBh[rn*40 + kt*16 + kq];
                bh[1] = *(const unsigned*)&sBh[rn*40 + kt*16 + kq + 8];
                if (PROD3) {
                    bl[0] = *(const unsigned*)&sBl[rn*40 + kt*16 + kq];
                    bl[1] = *(const unsigned*)&sBl[rn*40 + kt*16 + kq + 8];
                }
#pragma unroll
                for (int mt = 0; mt < 2; mt++) {
                    mma16816(c[mt][nt], ah[mt], bh);
                    if (PROD3) {
                        mma16816(c[mt][nt], al[mt], bh);
                        mma16816(c[mt][nt], ah[mt], bl);
                    }
                }
            }
        }
        __syncthreads();
    }

#pragma unroll
    for (int mt = 0; mt < 2; mt++) {
        int r0 = m0 + wm*32 + mt*16 + g;
#pragma unroll
        for (int nt = 0; nt < 8; nt++) {
            int col = n0 + wn*64 + nt*8 + kq;
            if (OM == 0) {
                *(float2*)&outF[(size_t)r0*D_ + col] = make_float2(c[mt][nt][0], c[mt][nt][1]);
                *(float2*)&outF[(size_t)(r0+8)*D_ + col] = make_float2(c[mt][nt][2], c[mt][nt][3]);
            } else if (OM == 1) {
                *(unsigned*)&outH[(size_t)r0*D_ + col]     = pack_bf16x2(c[mt][nt][0], c[mt][nt][1]);
                *(unsigned*)&outH[(size_t)(r0+8)*D_ + col] = pack_bf16x2(c[mt][nt][2], c[mt][nt][3]);
            } else if (OM == 2) {
                unsigned h0, l0, h1, l1;
                split2(c[mt][nt][0], c[mt][nt][1], h0, l0);
                split2(c[mt][nt][2], c[mt][nt][3], h1, l1);
                *(unsigned*)&outH[(size_t)r0*D_ + col] = h0;
                *(unsigned*)&outL[(size_t)r0*D_ + col] = l0;
                *(unsigned*)&outH[(size_t)(r0+8)*D_ + col] = h1;
                *(unsigned*)&outL[(size_t)(r0+8)*D_ + col] = l1;
            } else {
                unsigned h0, l0, h1, l1;
                split2(c[mt][nt][0], c[mt][nt][1], h0, l0);
                split2(c[mt][nt][2], c[mt][nt][3], h1, l1);
                int b0 = r0 / L_,  lA = r0 % L_;
                int b1i = (r0+8) / L_, lB = (r0+8) % L_;
                size_t t0 = ((size_t)b0*D_ + col)*L_ + lA;
                size_t t1 = ((size_t)b1i*D_ + col)*L_ + lB;
                *(unsigned short*)&outH[t0]      = (unsigned short)h0;
                *(unsigned short*)&outH[t0 + L_] = (unsigned short)(h0 >> 16);
                *(unsigned short*)&outL[t0]      = (unsigned short)l0;
                *(unsigned short*)&outL[t0 + L_] = (unsigned short)(l0 >> 16);
                *(unsigned short*)&outH[t1]      = (unsigned short)h1;
                *(unsigned short*)&outH[t1 + L_] = (unsigned short)(h1 >> 16);
                *(unsigned short*)&outL[t1]      = (unsigned short)l1;
                *(unsigned short*)&outL[t1 + L_] = (unsigned short)(l1 >> 16);
            }
        }
    }
}

// ---------------------------------------------------------------------------
// Kernel 4: flash attention, no-max softmax, 4 p-values per CTA.
// grid (H, 2, B*P/4). K/V loaded once, reused for all 4 p.
// ---------------------------------------------------------------------------
#define NP  4
#define AKH 0                          // K bf16 [256][40] = 20480 B
#define AVH 20480                      // V^T hi [32][264] = 16896 B
#define AVL 37376                      // V^T lo
#define ABI 54272                      // NP x 256 f32 = 4096 B
#define ASM_TOT (ABI + NP*256*4)

#define KP  40
#define VP  264

__global__ void __launch_bounds__(256, 2)
attn_kernel(const float* __restrict__ ehr_times, const float* __restrict__ itv) {
    extern __shared__ char sm[];
    int tid = threadIdx.x;
    int wid = tid >> 5, lane = tid & 31;
    int g  = lane >> 2;
    int kq = (lane & 3) * 2;
    int h    = blockIdx.x;
    int half = blockIdx.y;
    int bp4  = blockIdx.z;
    int b     = bp4 >> 3;
    int pbase = (bp4 & 7) * NP;

    {
        const __nv_bfloat16* kh = g_kh + (size_t)(b*L_)*D_ + h*HD_;
        for (int idx = tid; idx < 2048; idx += 256) {
            int r = idx >> 3, c4 = (idx & 7) * 4;
            *(uint2*)(sm + AKH + r*(KP*2) + c4*2) = *(const uint2*)(kh + r*D_ + c4);
        }
    }
    {
        const __nv_bfloat16* vh = g_vth + (size_t)(b*D_ + h*HD_)*L_;
        const __nv_bfloat16* vl = g_vtl + (size_t)(b*D_ + h*HD_)*L_;
        for (int idx = tid; idx < 1024; idx += 256) {
            int hd = idx >> 5, c8 = (idx & 31) * 8;
            *(uint4*)(sm + AVH + hd*(VP*2) + c8*2) = *(const uint4*)(vh + hd*L_ + c8);
            *(uint4*)(sm + AVL + hd*(VP*2) + c8*2) = *(const uint4*)(vl + hd*L_ + c8);
        }
    }
    for (int idx = tid; idx < NP*256; idx += 256) {
        int pi = idx >> 8, j = idx & 255;
        float s = itv[(b*P_ + pbase + pi)*2 + 0];
        float e = itv[(b*P_ + pbase + pi)*2 + 1];
        float ctr = 0.5f*(s+e);
        float t = ehr_times[b*L_ + j];
        ((float*)(sm + ABI))[idx] = (t >= s && t <= e) ? -fabsf(t - ctr) : -1e30f;
    }
    __syncthreads();

#pragma unroll 1
    for (int pi = 0; pi < NP; pi++) {
        int bp = b*P_ + pbase + pi;
        const float* sb = (const float*)(sm + ABI) + pi*256;

        unsigned qah[2][4];
        {
            size_t qrow = (size_t)bp*L_ + half*128 + wid*16;
#pragma unroll
            for (int kt = 0; kt < 2; kt++) {
                size_t base = (qrow + g)*D_ + h*HD_ + kt*16 + kq;
                qah[kt][0] = *(const unsigned*)(g_qh + base);
                qah[kt][1] = *(const unsigned*)(g_qh + base + 8*D_);
                qah[kt][2] = *(const unsigned*)(g_qh + base + 8);
                qah[kt][3] = *(const unsigned*)(g_qh + base + 8*D_ + 8);
            }
        }

        float d0 = 0.f, d1 = 0.f;
        float o[4][4];
#pragma unroll
        for (int nt = 0; nt < 4; nt++) { o[nt][0]=0.f; o[nt][1]=0.f; o[nt][2]=0.f; o[nt][3]=0.f; }

#pragma unroll 1
        for (int ch = 0; ch < 4; ch++) {
            float c[8][4];
#pragma unroll
            for (int nt = 0; nt < 8; nt++) { c[nt][0]=0.f; c[nt][1]=0.f; c[nt][2]=0.f; c[nt][3]=0.f; }
#pragma unroll
            for (int nt = 0; nt < 8; nt++) {
                const char* kb = sm + AKH + (ch*64 + nt*8 + g)*(KP*2);
#pragma unroll
                for (int kt = 0; kt < 2; kt++) {
                    unsigned bh[2];
                    bh[0] = *(const unsigned*)(kb + (kt*16 + kq)*2);
                    bh[1] = *(const unsigned*)(kb + (kt*16 + kq)*2 + 16);
                    mma16816(c[nt], qah[kt], bh);
                }
            }
#pragma unroll
            for (int nt = 0; nt < 8; nt++) {
                float2 bb = *(const float2*)&sb[ch*64 + nt*8 + kq];
                c[nt][0] = __expf(c[nt][0] + bb.x);
                c[nt][1] = __expf(c[nt][1] + bb.y);
                c[nt][2] = __expf(c[nt][2] + bb.x);
                c[nt][3] = __expf(c[nt][3] + bb.y);
                d0 += c[nt][0] + c[nt][1];
                d1 += c[nt][2] + c[nt][3];
            }
#pragma unroll
            for (int kt = 0; kt < 4; kt++) {
                unsigned ah[4], al[4];
                split2(c[2*kt][0],   c[2*kt][1],   ah[0], al[0]);
                split2(c[2*kt][2],   c[2*kt][3],   ah[1], al[1]);
                split2(c[2*kt+1][0], c[2*kt+1][1], ah[2], al[2]);
                split2(c[2*kt+1][2], c[2*kt+1][3], ah[3], al[3]);
#pragma unroll
                for (int nt = 0; nt < 4; nt++) {
                    const char* vb = sm + (nt*8 + g)*(VP*2) + (ch*64 + kt*16 + kq)*2;
                    unsigned bh[2], bl[2];
                    bh[0] = *(const unsigned*)(vb + AVH);
                    bh[1] = *(const unsigned*)(vb + AVH + 16);
                    bl[0] = *(const unsigned*)(vb + AVL);
                    bl[1] = *(const unsigned*)(vb + AVL + 16);
                    mma16816(o[nt], ah, bh);
                    mma16816(o[nt], al, bh);
                    mma16816(o[nt], ah, bl);
                }
            }
        }

        d0 += __shfl_xor_sync(0xffffffffu, d0, 1);
        d0 += __shfl_xor_sync(0xffffffffu, d0, 2);
        d1 += __shfl_xor_sync(0xffffffffu, d1, 1);
        d1 += __shfl_xor_sync(0xffffffffu, d1, 2);

        {
            float inv0 = 1.f / d0, inv1 = 1.f / d1;
            size_t orow = (size_t)bp*L_ + half*128 + wid*16;
#pragma unroll
            for (int nt = 0; nt < 4; nt++) {
                unsigned h0, l0, h1, l1;
                split2(o[nt][0]*inv0, o[nt][1]*inv0, h0, l0);
                split2(o[nt][2]*inv1, o[nt][3]*inv1, h1, l1);
                size_t i0 = (orow+g  )*D_ + h*HD_ + nt*8 + kq;
                size_t i1 = (orow+g+8)*D_ + h*HD_ + nt*8 + kq;
                *(unsigned*)&g_ctxh[i0] = h0;
                *(unsigned*)&g_ctxl[i0] = l0;
                *(unsigned*)&g_ctxh[i1] = h1;
                *(unsigned*)&g_ctxl[i1] = l1;
            }
        }
    }
}

// ---------------------------------------------------------------------------
extern "C" void kernel_launch(void* const* d_in, const int* in_sizes, int n_in,
                              void* d_out, int out_size) {
    const float* ehr       = (const float*)d_in[0];
    const float* ehr_times = (const float*)d_in[1];
    const float* itv       = (const float*)d_in[2];
    const float* w1        = (const float*)d_in[3];
    const float* b1        = (const float*)d_in[4];
    const float* w2        = (const float*)d_in[5];
    const float* b2        = (const float*)d_in[6];
    const float* wq        = (const float*)d_in[7];
    const float* bq        = (const float*)d_in[8];
    const float* wk        = (const float*)d_in[9];
    const float* bk        = (const float*)d_in[10];
    const float* wv        = (const float*)d_in[11];
    const float* bv        = (const float*)d_in[12];
    const float* wo        = (const float*)d_in[13];
    const float* bo        = (const float*)d_in[14];
    float* out = (float*)d_out;

    __nv_bfloat16 *p_eh, *p_el, *p_kh, *p_vth, *p_vtl, *p_qh;
    __nv_bfloat16 *p_hh, *p_hl, *p_w2qTh, *p_w2qTl;
    __nv_bfloat16 *p_ctxh, *p_ctxl, *p_woTh, *p_woTl;
    __nv_bfloat16 *p_wkT, *p_wvTh, *p_wvTl;
    float *p_bq2;
    cudaGetSymbolAddress((void**)&p_eh, g_eh);
    cudaGetSymbolAddress((void**)&p_el, g_el);
    cudaGetSymbolAddress((void**)&p_kh, g_kh);
    cudaGetSymbolAddress((void**)&p_vth, g_vth);
    cudaGetSymbolAddress((void**)&p_vtl, g_vtl);
    cudaGetSymbolAddress((void**)&p_qh, g_qh);
    cudaGetSymbolAddress((void**)&p_hh, g_hh);
    cudaGetSymbolAddress((void**)&p_hl, g_hl);
    cudaGetSymbolAddress((void**)&p_w2qTh, g_w2qTh);
    cudaGetSymbolAddress((void**)&p_w2qTl, g_w2qTl);
    cudaGetSymbolAddress((void**)&p_ctxh, g_ctxh);
    cudaGetSymbolAddress((void**)&p_ctxl, g_ctxl);
    cudaGetSymbolAddress((void**)&p_woTh, g_woTh);
    cudaGetSymbolAddress((void**)&p_woTl, g_woTl);
    cudaGetSymbolAddress((void**)&p_wkT, g_wkT);
    cudaGetSymbolAddress((void**)&p_wvTh, g_wvTh);
    cudaGetSymbolAddress((void**)&p_wvTl, g_wvTl);
    cudaGetSymbolAddress((void**)&p_bq2, g_bq2);

    fuse_w_kernel<<<DH_, D_>>>(w2, wq, b2, bq);
    prep_split_kernel<<<D_, D_>>>(wo, wk, wv);
    split_ehr_kernel<<<B_*L_, 256>>>(ehr);
    h_kernel<<<B_*P_*L_/32, 256>>>(ehr_times, itv, w1, b1);

    // K = ehr @ wk + bk  (single-product, single bf16 out)
    gemm_kernel<D_, false, 1><<<dim3(8, 2), 256>>>(
        p_eh, p_eh, p_wkT, p_wkT, bk, nullptr, p_kh, nullptr);
    // V = ehr @ wv + bv  (3-product, TRANSPOSED split hi/lo out)
    gemm_kernel<D_, true, 3><<<dim3(8, 2), 256>>>(
        p_eh, p_el, p_wvTh, p_wvTl, bv, nullptr, p_vth, p_vtl);
    // q = h @ W2q' + bq2'  (3-product, single bf16 out)
    gemm_kernel<DH_, true, 1><<<dim3(256, 2), 256>>>(
        p_hh, p_hl, p_w2qTh, p_w2qTl, p_bq2, nullptr, p_qh, nullptr);

    cudaFuncSetAttribute(attn_kernel, cudaFuncAttributeMaxDynamicSharedMemorySize, ASM_TOT);
    attn_kernel<<<dim3(H_, 2, B_*P_/NP), 256, ASM_TOT>>>(ehr_times, itv);

    // out = ctx @ wo + bo  (3-product, fp32 out)
    gemm_kernel<D_, true, 0><<<dim3(256, 2), 256>>>(
        p_ctxh, p_ctxl, p_woTh, p_woTl, bo, out, nullptr, nullptr);
}

// round 16
// speedup vs baseline: 1.0602x; 1.0602x over previous
#include <cuda_runtime.h>
#include <cuda_bf16.h>
#include <math.h>
#include <cstdint>

#define B_  4
#define L_  256
#define D_  256
#define P_  32
#define H_  8
#define HD_ 32
#define DH_ 128   // D/2

// ======================= mma.sync bf16 =====================================
__device__ __forceinline__ void mma16816(float* c, const unsigned* a, const unsigned* b) {
    asm volatile("mma.sync.aligned.m16n8k16.row.col.f32.bf16.bf16.f32 "
        "{%0,%1,%2,%3}, {%4,%5,%6,%7}, {%8,%9}, {%0,%1,%2,%3};"
        : "+f"(c[0]), "+f"(c[1]), "+f"(c[2]), "+f"(c[3])
        : "r"(a[0]), "r"(a[1]), "r"(a[2]), "r"(a[3]), "r"(b[0]), "r"(b[1]));
}
__device__ __forceinline__ unsigned pack_bf16x2(float x0, float x1) {
    __nv_bfloat162 t = __floats2bfloat162_rn(x0, x1);
    return *reinterpret_cast<unsigned*>(&t);
}
// fast split: hi = rn-rounded bf16 pair (1 cvt), lo from exact shift-expansion
__device__ __forceinline__ void split2(float x0, float x1, unsigned& whi, unsigned& wlo) {
    whi = pack_bf16x2(x0, x1);
    float h0 = __uint_as_float(whi << 16);
    float h1 = __uint_as_float(whi & 0xffff0000u);
    wlo = pack_bf16x2(x0 - h0, x1 - h1);
}
__device__ __forceinline__ void split1(float x, __nv_bfloat16& h, __nv_bfloat16& l) {
    h = __float2bfloat16(x);
    l = __float2bfloat16(x - __bfloat162float(h));
}

// ======================= scratch =========================================
__device__ __nv_bfloat16 g_eh[B_*L_*D_];        // ehr hi
__device__ __nv_bfloat16 g_el[B_*L_*D_];        // ehr lo
__device__ __nv_bfloat16 g_kh[B_*L_*D_];        // K single bf16
__device__ __nv_bfloat16 g_vth[B_*D_*L_];       // V^T hi [(b*D + c)][l]
__device__ __nv_bfloat16 g_vtl[B_*D_*L_];       // V^T lo
__device__ __nv_bfloat16 g_qh[B_*P_*L_*D_];     // q single bf16
__device__ __nv_bfloat16 g_ctxh[B_*P_*L_*D_];
__device__ __nv_bfloat16 g_ctxl[B_*P_*L_*D_];
__device__ __nv_bfloat16 g_hh[B_*P_*L_*DH_];    // h single bf16
__device__ __nv_bfloat16 g_woTh[D_*D_];         // [n][k]
__device__ __nv_bfloat16 g_woTl[D_*D_];
__device__ __nv_bfloat16 g_wkT[D_*D_];          // [n][k] single bf16
__device__ __nv_bfloat16 g_wvTh[D_*D_];         // [n][k]
__device__ __nv_bfloat16 g_wvTl[D_*D_];
__device__ __nv_bfloat16 g_w2qT[D_*DH_];        // [n][k] single bf16, scale folded
__device__ float g_W2q[DH_*D_];
__device__ float g_bq2[D_];                     // scale folded

// ---------------------------------------------------------------------------
// Kernel 1: W2q = w2 @ wq, bq2 = scale*(b2 @ wq + bq)
// ---------------------------------------------------------------------------
__global__ void fuse_w_kernel(const float* __restrict__ w2, const float* __restrict__ wq,
                              const float* __restrict__ b2, const float* __restrict__ bq) {
    int j = blockIdx.x, c = threadIdx.x;
    float acc = 0.f;
    for (int k = 0; k < D_; k++) acc = fmaf(w2[j*D_+k], wq[k*D_+c], acc);
    g_W2q[j*D_+c] = acc;
    if (j == 0) {
        float a = 0.f;
        for (int k = 0; k < D_; k++) a = fmaf(b2[k], wq[k*D_+c], a);
        g_bq2[c] = 0.17677669529663687f * (a + bq[c]);
    }
}

// ---------------------------------------------------------------------------
// Kernel 1b: transpose+split weights
// ---------------------------------------------------------------------------
__global__ void prep_split_kernel(const float* __restrict__ wo,
                                  const float* __restrict__ wk,
                                  const float* __restrict__ wv) {
    int n = blockIdx.x, k = threadIdx.x;
    __nv_bfloat16 h, l;
    split1(wo[k*D_ + n], h, l);
    g_woTh[n*D_ + k] = h;
    g_woTl[n*D_ + k] = l;
    g_wkT[n*D_ + k] = __float2bfloat16(wk[k*D_ + n]);
    split1(wv[k*D_ + n], h, l);
    g_wvTh[n*D_ + k] = h;
    g_wvTl[n*D_ + k] = l;
    if (k < DH_) {
        g_w2qT[n*DH_ + k] = __float2bfloat16(0.17677669529663687f * g_W2q[k*D_ + n]);
    }
}

// ---------------------------------------------------------------------------
// Kernel 1c: split ehr into hi/lo bf16
// ---------------------------------------------------------------------------
__global__ void split_ehr_kernel(const float* __restrict__ ehr) {
    int i = blockIdx.x * 256 + threadIdx.x;
    __nv_bfloat16 h, l;
    split1(ehr[i], h, l);
    g_eh[i] = h;
    g_el[i] = l;
}

// ---------------------------------------------------------------------------
// Kernel 3: time features -> MLP -> gelu -> h (single bf16)
// ---------------------------------------------------------------------------
__global__ void h_kernel(const float* __restrict__ ehr_times, const float* __restrict__ itv,
                         const float* __restrict__ w1, const float* __restrict__ b1) {
    __shared__ float3 stf[32];
    int tid = threadIdx.x;
    int g0 = blockIdx.x * 32;
    int b  = g0 / (P_*L_);
    int p  = (g0 / L_) % P_;
    int l0 = g0 % L_;
    if (tid < 32) {
        float t = ehr_times[b*L_ + l0 + tid];
        float s = itv[(b*P_+p)*2 + 0];
        float e = itv[(b*P_+p)*2 + 1];
        float ds = t - s, de = e - t;
        float x  = ds * de;
        float sg = 1.f / (1.f + expf(-x));
        stf[tid] = make_float3(ds, de, sg);
    }
    __syncthreads();
    for (int i = tid; i < 32*DH_; i += 256) {
        int r = i >> 7, j = i & 127;
        float3 tf = stf[r];
        float z = tf.x*w1[j] + tf.y*w1[DH_+j] + tf.z*w1[2*DH_+j] + b1[j];
        float v = 0.5f * z * (1.f + erff(z * 0.70710678118654752f));
        g_hh[(size_t)g0*DH_ + i] = __float2bfloat16(v);
    }
}

// ---------------------------------------------------------------------------
// Generic bf16 GEMM. PROD3: hi/lo 3-product.
// OM: 0 fp32, 1 single bf16, 2 split bf16, 3 split bf16 TRANSPOSED [(b*D+n)][l]
// ---------------------------------------------------------------------------
template<int K, bool PROD3, int OM>
__global__ void __launch_bounds__(256)
gemm_kernel(const __nv_bfloat16* __restrict__ Ah, const __nv_bfloat16* __restrict__ Al,
            const __nv_bfloat16* __restrict__ BTh, const __nv_bfloat16* __restrict__ BTl,
            const float* __restrict__ bias,
            float* __restrict__ outF,
            __nv_bfloat16* __restrict__ outH, __nv_bfloat16* __restrict__ outL) {
    __shared__ __nv_bfloat16 sAh[128*40], sAl[128*40], sBh[128*40], sBl[128*40];
    int tid = threadIdx.x, wid = tid >> 5, lane = tid & 31;
    int g = lane >> 2, kq = (lane & 3) * 2;
    int wm = wid & 3, wn = wid >> 2;
    int m0 = blockIdx.x * 128, n0 = blockIdx.y * 128;

    float c[2][8][4];
#pragma unroll
    for (int nt = 0; nt < 8; nt++) {
        float2 bb = *(const float2*)&bias[n0 + wn*64 + nt*8 + kq];
#pragma unroll
        for (int mt = 0; mt < 2; mt++) {
            c[mt][nt][0] = bb.x; c[mt][nt][1] = bb.y;
            c[mt][nt][2] = bb.x; c[mt][nt][3] = bb.y;
        }
    }

    for (int kc = 0; kc < K; kc += 32) {
        for (int idx = tid; idx < 1024; idx += 256) {
            int r = idx >> 3, c4 = (idx & 7) * 4;
            *(uint2*)&sAh[r*40 + c4] = *(const uint2*)&Ah[(size_t)(m0+r)*K + kc + c4];
            *(uint2*)&sBh[r*40 + c4] = *(const uint2*)&BTh[(size_t)(n0+r)*K + kc + c4];
            if (PROD3) {
                *(uint2*)&sAl[r*40 + c4] = *(const uint2*)&Al[(size_t)(m0+r)*K + kc + c4];
                *(uint2*)&sBl[r*40 + c4] = *(const uint2*)&BTl[(size_t)(n0+r)*K + kc + c4];
            }
        }
        __syncthreads();
#pragma unroll
        for (int kt = 0; kt < 2; kt++) {
            unsigned ah[2][4], al[2][4];
#pragma unroll
            for (int mt = 0; mt < 2; mt++) {
                int rb = wm*32 + mt*16;
                ah[mt][0] = *(const unsigned*)&sAh[(rb+g  )*40 + kt*16 + kq];
                ah[mt][1] = *(const unsigned*)&sAh[(rb+g+8)*40 + kt*16 + kq];
                ah[mt][2] = *(const unsigned*)&sAh[(rb+g  )*40 + kt*16 + kq + 8];
                ah[mt][3] = *(const unsigned*)&sAh[(rb+g+8)*40 + kt*16 + kq + 8];
                if (PROD3) {
                    al[mt][0] = *(const unsigned*)&sAl[(rb+g  )*40 + kt*16 + kq];
                    al[mt][1] = *(const unsigned*)&sAl[(rb+g+8)*40 + kt*16 + kq];
                    al[mt][2] = *(const unsigned*)&sAl[(rb+g  )*40 + kt*16 + kq + 8];
                    al[mt][3] = *(const unsigned*)&sAl[(rb+g+8)*40 + kt*16 + kq + 8];
                }
            }
#pragma unroll
            for (int nt = 0; nt < 8; nt++) {
                int rn = wn*64 + nt*8 + g;
                unsigned bh[2], bl[2];
                bh[0] = *(const unsigned*)&sBh[rn*40 + kt*16 + kq];
                bh[1] = *(const unsigned*)&sBh[rn*40 + kt*16 + kq + 8];
                if (PROD3) {
                    bl[0] = *(const unsigned*)&sBl[rn*40 + kt*16 + kq];
                    bl[1] = *(const unsigned*)&sBl[rn*40 + kt*16 + kq + 8];
                }
#pragma unroll
                for (int mt = 0; mt < 2; mt++) {
                    mma16816(c[mt][nt], ah[mt], bh);
                    if (PROD3) {
                        mma16816(c[mt][nt], al[mt], bh);
                        mma16816(c[mt][nt], ah[mt], bl);
                    }
                }
            }
        }
        __syncthreads();
    }

#pragma unroll
    for (int mt = 0; mt < 2; mt++) {
        int r0 = m0 + wm*32 + mt*16 + g;
#pragma unroll
        for (int nt = 0; nt < 8; nt++) {
            int col = n0 + wn*64 + nt*8 + kq;
            if (OM == 0) {
                *(float2*)&outF[(size_t)r0*D_ + col] = make_float2(c[mt][nt][0], c[mt][nt][1]);
                *(float2*)&outF[(size_t)(r0+8)*D_ + col] = make_float2(c[mt][nt][2], c[mt][nt][3]);
            } else if (OM == 1) {
                *(unsigned*)&outH[(size_t)r0*D_ + col]     = pack_bf16x2(c[mt][nt][0], c[mt][nt][1]);
                *(unsigned*)&outH[(size_t)(r0+8)*D_ + col] = pack_bf16x2(c[mt][nt][2], c[mt][nt][3]);
            } else if (OM == 2) {
                unsigned h0, l0, h1, l1;
                split2(c[mt][nt][0], c[mt][nt][1], h0, l0);
                split2(c[mt][nt][2], c[mt][nt][3], h1, l1);
                *(unsigned*)&outH[(size_t)r0*D_ + col] = h0;
                *(unsigned*)&outL[(size_t)r0*D_ + col] = l0;
                *(unsigned*)&outH[(size_t)(r0+8)*D_ + col] = h1;
                *(unsigned*)&outL[(size_t)(r0+8)*D_ + col] = l1;
            } else {
                unsigned h0, l0, h1, l1;
                split2(c[mt][nt][0], c[mt][nt][1], h0, l0);
                split2(c[mt][nt][2], c[mt][nt][3], h1, l1);
                int b0 = r0 / L_,  lA = r0 % L_;
                int b1i = (r0+8) / L_, lB = (r0+8) % L_;
                size_t t0 = ((size_t)b0*D_ + col)*L_ + lA;
                size_t t1 = ((size_t)b1i*D_ + col)*L_ + lB;
                *(unsigned short*)&outH[t0]      = (unsigned short)h0;
                *(unsigned short*)&outH[t0 + L_] = (unsigned short)(h0 >> 16);
                *(unsigned short*)&outL[t0]      = (unsigned short)l0;
                *(unsigned short*)&outL[t0 + L_] = (unsigned short)(l0 >> 16);
                *(unsigned short*)&outH[t1]      = (unsigned short)h1;
                *(unsigned short*)&outH[t1 + L_] = (unsigned short)(h1 >> 16);
                *(unsigned short*)&outL[t1]      = (unsigned short)l1;
                *(unsigned short*)&outL[t1 + L_] = (unsigned short)(l1 >> 16);
            }
        }
    }
}

// ---------------------------------------------------------------------------
// Kernel 4: flash attention, no-max softmax (R14 grid: (H, 2, B*P))
// ---------------------------------------------------------------------------
#define AKH 0                          // K bf16 [256][40] = 20480 B
#define AVH 20480                      // V^T hi [32][264] = 16896 B
#define AVL 37376                      // V^T lo
#define ABI 54272                      // 256 f32
#define ASM_TOT 55296
#define KP  40
#define VP  264

__global__ void __launch_bounds__(256, 2)
attn_kernel(const float* __restrict__ ehr_times, const float* __restrict__ itv) {
    extern __shared__ char sm[];
    int tid = threadIdx.x;
    int wid = tid >> 5, lane = tid & 31;
    int g  = lane >> 2;
    int kq = (lane & 3) * 2;
    int h    = blockIdx.x;
    int half = blockIdx.y;
    int bp   = blockIdx.z;
    int b = bp >> 5;

    {
        const __nv_bfloat16* kh = g_kh + (size_t)(b*L_)*D_ + h*HD_;
        for (int idx = tid; idx < 2048; idx += 256) {
            int r = idx >> 3, c4 = (idx & 7) * 4;
            *(uint2*)(sm + AKH + r*(KP*2) + c4*2) = *(const uint2*)(kh + r*D_ + c4);
        }
    }
    {
        const __nv_bfloat16* vh = g_vth + (size_t)(b*D_ + h*HD_)*L_;
        const __nv_bfloat16* vl = g_vtl + (size_t)(b*D_ + h*HD_)*L_;
        for (int idx = tid; idx < 1024; idx += 256) {
            int hd = idx >> 5, c8 = (idx & 31) * 8;
            *(uint4*)(sm + AVH + hd*(VP*2) + c8*2) = *(const uint4*)(vh + hd*L_ + c8);
            *(uint4*)(sm + AVL + hd*(VP*2) + c8*2) = *(const uint4*)(vl + hd*L_ + c8);
        }
    }
    {
        float s = itv[bp*2 + 0];
        float e = itv[bp*2 + 1];
        float ctr = 0.5f*(s+e);
        float t = ehr_times[b*L_ + tid];
        ((float*)(sm + ABI))[tid] = (t >= s && t <= e) ? -fabsf(t - ctr) : -1e30f;
    }

    unsigned qah[2][4];
    {
        size_t qrow = (size_t)bp*L_ + half*128 + wid*16;
#pragma unroll
        for (int kt = 0; kt < 2; kt++) {
            size_t base = (qrow + g)*D_ + h*HD_ + kt*16 + kq;
            qah[kt][0] = *(const unsigned*)(g_qh + base);
            qah[kt][1] = *(const unsigned*)(g_qh + base + 8*D_);
            qah[kt][2] = *(const unsigned*)(g_qh + base + 8);
            qah[kt][3] = *(const unsigned*)(g_qh + base + 8*D_ + 8);
        }
    }
    __syncthreads();

    const float* sb = (const float*)(sm + ABI);
    float d0 = 0.f, d1 = 0.f;
    float o[4][4];
#pragma unroll
    for (int nt = 0; nt < 4; nt++) { o[nt][0]=0.f; o[nt][1]=0.f; o[nt][2]=0.f; o[nt][3]=0.f; }

#pragma unroll 1
    for (int ch = 0; ch < 4; ch++) {
        float c[8][4];
#pragma unroll
        for (int nt = 0; nt < 8; nt++) { c[nt][0]=0.f; c[nt][1]=0.f; c[nt][2]=0.f; c[nt][3]=0.f; }
#pragma unroll
        for (int nt = 0; nt < 8; nt++) {
            const char* kb = sm + AKH + (ch*64 + nt*8 + g)*(KP*2);
#pragma unroll
            for (int kt = 0; kt < 2; kt++) {
                unsigned bh[2];
                bh[0] = *(const unsigned*)(kb + (kt*16 + kq)*2);
                bh[1] = *(const unsigned*)(kb + (kt*16 + kq)*2 + 16);
                mma16816(c[nt], qah[kt], bh);
            }
        }
#pragma unroll
        for (int nt = 0; nt < 8; nt++) {
            float2 bb = *(const float2*)&sb[ch*64 + nt*8 + kq];
            c[nt][0] = __expf(c[nt][0] + bb.x);
            c[nt][1] = __expf(c[nt][1] + bb.y);
            c[nt][2] = __expf(c[nt][2] + bb.x);
            c[nt][3] = __expf(c[nt][3] + bb.y);
            d0 += c[nt][0] + c[nt][1];
            d1 += c[nt][2] + c[nt][3];
        }
#pragma unroll
        for (int kt = 0; kt < 4; kt++) {
            unsigned ah[4], al[4];
            split2(c[2*kt][0],   c[2*kt][1],   ah[0], al[0]);
            split2(c[2*kt][2],   c[2*kt][3],   ah[1], al[1]);
            split2(c[2*kt+1][0], c[2*kt+1][1], ah[2], al[2]);
            split2(c[2*kt+1][2], c[2*kt+1][3], ah[3], al[3]);
#pragma unroll
            for (int nt = 0; nt < 4; nt++) {
                const char* vb = sm + (nt*8 + g)*(VP*2) + (ch*64 + kt*16 + kq)*2;
                unsigned bh[2], bl[2];
                bh[0] = *(const unsigned*)(vb + AVH);
                bh[1] = *(const unsigned*)(vb + AVH + 16);
                bl[0] = *(const unsigned*)(vb + AVL);
                bl[1] = *(const unsigned*)(vb + AVL + 16);
                mma16816(o[nt], ah, bh);
                mma16816(o[nt], al, bh);
                mma16816(o[nt], ah, bl);
            }
        }
    }

    d0 += __shfl_xor_sync(0xffffffffu, d0, 1);
    d0 += __shfl_xor_sync(0xffffffffu, d0, 2);
    d1 += __shfl_xor_sync(0xffffffffu, d1, 1);
    d1 += __shfl_xor_sync(0xffffffffu, d1, 2);

    {
        float inv0 = 1.f / d0, inv1 = 1.f / d1;
        size_t orow = (size_t)bp*L_ + half*128 + wid*16;
#pragma unroll
        for (int nt = 0; nt < 4; nt++) {
            unsigned h0, l0, h1, l1;
            split2(o[nt][0]*inv0, o[nt][1]*inv0, h0, l0);
            split2(o[nt][2]*inv1, o[nt][3]*inv1, h1, l1);
            size_t i0 = (orow+g  )*D_ + h*HD_ + nt*8 + kq;
            size_t i1 = (orow+g+8)*D_ + h*HD_ + nt*8 + kq;
            *(unsigned*)&g_ctxh[i0] = h0;
            *(unsigned*)&g_ctxl[i0] = l0;
            *(unsigned*)&g_ctxh[i1] = h1;
            *(unsigned*)&g_ctxl[i1] = l1;
        }
    }
}

// ---------------------------------------------------------------------------
extern "C" void kernel_launch(void* const* d_in, const int* in_sizes, int n_in,
                              void* d_out, int out_size) {
    const float* ehr       = (const float*)d_in[0];
    const float* ehr_times = (const float*)d_in[1];
    const float* itv       = (const float*)d_in[2];
    const float* w1        = (const float*)d_in[3];
    const float* b1        = (const float*)d_in[4];
    const float* w2        = (const float*)d_in[5];
    const float* b2        = (const float*)d_in[6];
    const float* wq        = (const float*)d_in[7];
    const float* bq        = (const float*)d_in[8];
    const float* wk        = (const float*)d_in[9];
    const float* bk        = (const float*)d_in[10];
    const float* wv        = (const float*)d_in[11];
    const float* bv        = (const float*)d_in[12];
    const float* wo        = (const float*)d_in[13];
    const float* bo        = (const float*)d_in[14];
    float* out = (float*)d_out;

    __nv_bfloat16 *p_eh, *p_el, *p_kh, *p_vth, *p_vtl, *p_qh;
    __nv_bfloat16 *p_hh, *p_w2qT;
    __nv_bfloat16 *p_ctxh, *p_ctxl, *p_woTh, *p_woTl;
    __nv_bfloat16 *p_wkT, *p_wvTh, *p_wvTl;
    float *p_bq2;
    cudaGetSymbolAddress((void**)&p_eh, g_eh);
    cudaGetSymbolAddress((void**)&p_el, g_el);
    cudaGetSymbolAddress((void**)&p_kh, g_kh);
    cudaGetSymbolAddress((void**)&p_vth, g_vth);
    cudaGetSymbolAddress((void**)&p_vtl, g_vtl);
    cudaGetSymbolAddress((void**)&p_qh, g_qh);
    cudaGetSymbolAddress((void**)&p_hh, g_hh);
    cudaGetSymbolAddress((void**)&p_w2qT, g_w2qT);
    cudaGetSymbolAddress((void**)&p_ctxh, g_ctxh);
    cudaGetSymbolAddress((void**)&p_ctxl, g_ctxl);
    cudaGetSymbolAddress((void**)&p_woTh, g_woTh);
    cudaGetSymbolAddress((void**)&p_woTl, g_woTl);
    cudaGetSymbolAddress((void**)&p_wkT, g_wkT);
    cudaGetSymbolAddress((void**)&p_wvTh, g_wvTh);
    cudaGetSymbolAddress((void**)&p_wvTl, g_wvTl);
    cudaGetSymbolAddress((void**)&p_bq2, g_bq2);

    fuse_w_kernel<<<DH_, D_>>>(w2, wq, b2, bq);
    prep_split_kernel<<<D_, D_>>>(wo, wk, wv);
    split_ehr_kernel<<<B_*L_, 256>>>(ehr);
    h_kernel<<<B_*P_*L_/32, 256>>>(ehr_times, itv, w1, b1);

    // K = ehr @ wk + bk  (single-product, single bf16 out)
    gemm_kernel<D_, false, 1><<<dim3(8, 2), 256>>>(
        p_eh, p_eh, p_wkT, p_wkT, bk, nullptr, p_kh, nullptr);
    // V = ehr @ wv + bv  (3-product, TRANSPOSED split hi/lo out)
    gemm_kernel<D_, true, 3><<<dim3(8, 2), 256>>>(
        p_eh, p_el, p_wvTh, p_wvTl, bv, nullptr, p_vth, p_vtl);
    // q = h @ W2q' + bq2'  (SINGLE-product, single bf16 out)
    gemm_kernel<DH_, false, 1><<<dim3(256, 2), 256>>>(
        p_hh, p_hh, p_w2qT, p_w2qT, p_bq2, nullptr, p_qh, nullptr);

    cudaFuncSetAttribute(attn_kernel, cudaFuncAttributeMaxDynamicSharedMemorySize, ASM_TOT);
    attn_kernel<<<dim3(H_, 2, B_*P_), 256, ASM_TOT>>>(ehr_times, itv);

    // out = ctx @ wo + bo  (3-product, fp32 out)
    gemm_kernel<D_, true, 0><<<dim3(256, 2), 256>>>(
        p_ctxh, p_ctxl, p_woTh, p_woTl, bo, out, nullptr, nullptr);
}

// round 17
// speedup vs baseline: 1.1087x; 1.0457x over previous
#include <cuda_runtime.h>
#include <cuda_bf16.h>
#include <cuda_fp16.h>
#include <math.h>
#include <cstdint>

#define B_  4
#define L_  256
#define D_  256
#define P_  32
#define H_  8
#define HD_ 32
#define DH_ 128   // D/2

// ======================= mma.sync =====================================
__device__ __forceinline__ void mma16816(float* c, const unsigned* a, const unsigned* b) {
    asm volatile("mma.sync.aligned.m16n8k16.row.col.f32.bf16.bf16.f32 "
        "{%0,%1,%2,%3}, {%4,%5,%6,%7}, {%8,%9}, {%0,%1,%2,%3};"
        : "+f"(c[0]), "+f"(c[1]), "+f"(c[2]), "+f"(c[3])
        : "r"(a[0]), "r"(a[1]), "r"(a[2]), "r"(a[3]), "r"(b[0]), "r"(b[1]));
}
__device__ __forceinline__ void mma16816h(float* c, const unsigned* a, const unsigned* b) {
    asm volatile("mma.sync.aligned.m16n8k16.row.col.f32.f16.f16.f32 "
        "{%0,%1,%2,%3}, {%4,%5,%6,%7}, {%8,%9}, {%0,%1,%2,%3};"
        : "+f"(c[0]), "+f"(c[1]), "+f"(c[2]), "+f"(c[3])
        : "r"(a[0]), "r"(a[1]), "r"(a[2]), "r"(a[3]), "r"(b[0]), "r"(b[1]));
}
__device__ __forceinline__ unsigned pack_bf16x2(float x0, float x1) {
    __nv_bfloat162 t = __floats2bfloat162_rn(x0, x1);
    return *reinterpret_cast<unsigned*>(&t);
}
__device__ __forceinline__ unsigned pack_f16x2(float x0, float x1) {
    __half2 t = __floats2half2_rn(x0, x1);
    return *reinterpret_cast<unsigned*>(&t);
}
// bf16 split: hi = rn pair, lo from exact shift-expansion
__device__ __forceinline__ void split2(float x0, float x1, unsigned& whi, unsigned& wlo) {
    whi = pack_bf16x2(x0, x1);
    float h0 = __uint_as_float(whi << 16);
    float h1 = __uint_as_float(whi & 0xffff0000u);
    wlo = pack_bf16x2(x0 - h0, x1 - h1);
}
// fp16 split
__device__ __forceinline__ void split2h(float x0, float x1, unsigned& whi, unsigned& wlo) {
    whi = pack_f16x2(x0, x1);
    __half2 hv = *reinterpret_cast<__half2*>(&whi);
    wlo = pack_f16x2(x0 - __half2float(hv.x), x1 - __half2float(hv.y));
}
__device__ __forceinline__ void split1(float x, __nv_bfloat16& h, __nv_bfloat16& l) {
    h = __float2bfloat16(x);
    l = __float2bfloat16(x - __bfloat162float(h));
}

// ======================= scratch =========================================
__device__ __nv_bfloat16 g_eh[B_*L_*D_];        // ehr hi
__device__ __nv_bfloat16 g_el[B_*L_*D_];        // ehr lo
__device__ __nv_bfloat16 g_kh[B_*L_*D_];        // K single bf16
__device__ unsigned short g_vt[B_*D_*L_];       // V^T single fp16 [(b*D + c)][l]
__device__ __nv_bfloat16 g_qh[B_*P_*L_*D_];     // q single bf16
__device__ __nv_bfloat16 g_ctxh[B_*P_*L_*D_];
__device__ __nv_bfloat16 g_ctxl[B_*P_*L_*D_];
__device__ __nv_bfloat16 g_hh[B_*P_*L_*DH_];    // h single bf16
__device__ __nv_bfloat16 g_woTh[D_*D_];         // [n][k]
__device__ __nv_bfloat16 g_woTl[D_*D_];
__device__ __nv_bfloat16 g_wkT[D_*D_];          // [n][k] single bf16
__device__ __nv_bfloat16 g_wvTh[D_*D_];         // [n][k]
__device__ __nv_bfloat16 g_wvTl[D_*D_];
__device__ __nv_bfloat16 g_w2qT[D_*DH_];        // [n][k] single bf16, scale folded
__device__ float g_W2q[DH_*D_];
__device__ float g_bq2[D_];                     // scale folded

// ---------------------------------------------------------------------------
// Kernel 1: W2q = w2 @ wq, bq2 = scale*(b2 @ wq + bq)
// ---------------------------------------------------------------------------
__global__ void fuse_w_kernel(const float* __restrict__ w2, const float* __restrict__ wq,
                              const float* __restrict__ b2, const float* __restrict__ bq) {
    int j = blockIdx.x, c = threadIdx.x;
    float acc = 0.f;
    for (int k = 0; k < D_; k++) acc = fmaf(w2[j*D_+k], wq[k*D_+c], acc);
    g_W2q[j*D_+c] = acc;
    if (j == 0) {
        float a = 0.f;
        for (int k = 0; k < D_; k++) a = fmaf(b2[k], wq[k*D_+c], a);
        g_bq2[c] = 0.17677669529663687f * (a + bq[c]);
    }
}

// ---------------------------------------------------------------------------
// Kernel 1b: transpose+split weights
// ---------------------------------------------------------------------------
__global__ void prep_split_kernel(const float* __restrict__ wo,
                                  const float* __restrict__ wk,
                                  const float* __restrict__ wv) {
    int n = blockIdx.x, k = threadIdx.x;
    __nv_bfloat16 h, l;
    split1(wo[k*D_ + n], h, l);
    g_woTh[n*D_ + k] = h;
    g_woTl[n*D_ + k] = l;
    g_wkT[n*D_ + k] = __float2bfloat16(wk[k*D_ + n]);
    split1(wv[k*D_ + n], h, l);
    g_wvTh[n*D_ + k] = h;
    g_wvTl[n*D_ + k] = l;
    if (k < DH_) {
        g_w2qT[n*DH_ + k] = __float2bfloat16(0.17677669529663687f * g_W2q[k*D_ + n]);
    }
}

// ---------------------------------------------------------------------------
// Kernel 1c: split ehr into hi/lo bf16
// ---------------------------------------------------------------------------
__global__ void split_ehr_kernel(const float* __restrict__ ehr) {
    int i = blockIdx.x * 256 + threadIdx.x;
    __nv_bfloat16 h, l;
    split1(ehr[i], h, l);
    g_eh[i] = h;
    g_el[i] = l;
}

// ---------------------------------------------------------------------------
// Kernel 3: time features -> MLP -> gelu -> h (single bf16)
// ---------------------------------------------------------------------------
__global__ void h_kernel(const float* __restrict__ ehr_times, const float* __restrict__ itv,
                         const float* __restrict__ w1, const float* __restrict__ b1) {
    __shared__ float3 stf[32];
    int tid = threadIdx.x;
    int g0 = blockIdx.x * 32;
    int b  = g0 / (P_*L_);
    int p  = (g0 / L_) % P_;
    int l0 = g0 % L_;
    if (tid < 32) {
        float t = ehr_times[b*L_ + l0 + tid];
        float s = itv[(b*P_+p)*2 + 0];
        float e = itv[(b*P_+p)*2 + 1];
        float ds = t - s, de = e - t;
        float x  = ds * de;
        float sg = 1.f / (1.f + expf(-x));
        stf[tid] = make_float3(ds, de, sg);
    }
    __syncthreads();
    for (int i = tid; i < 32*DH_; i += 256) {
        int r = i >> 7, j = i & 127;
        float3 tf = stf[r];
        float z = tf.x*w1[j] + tf.y*w1[DH_+j] + tf.z*w1[2*DH_+j] + b1[j];
        float v = 0.5f * z * (1.f + erff(z * 0.70710678118654752f));
        g_hh[(size_t)g0*DH_ + i] = __float2bfloat16(v);
    }
}

// ---------------------------------------------------------------------------
// Generic bf16 GEMM. PROD3: hi/lo 3-product.
// OM: 0 fp32, 1 single bf16, 2 split bf16, 3 split bf16 transposed,
//     4 single FP16 TRANSPOSED [(b*D+n)][l]
// ---------------------------------------------------------------------------
template<int K, bool PROD3, int OM>
__global__ void __launch_bounds__(256)
gemm_kernel(const __nv_bfloat16* __restrict__ Ah, const __nv_bfloat16* __restrict__ Al,
            const __nv_bfloat16* __restrict__ BTh, const __nv_bfloat16* __restrict__ BTl,
            const float* __restrict__ bias,
            float* __restrict__ outF,
            __nv_bfloat16* __restrict__ outH, __nv_bfloat16* __restrict__ outL,
            unsigned short* __restrict__ outHalf) {
    __shared__ __nv_bfloat16 sAh[128*40], sAl[128*40], sBh[128*40], sBl[128*40];
    int tid = threadIdx.x, wid = tid >> 5, lane = tid & 31;
    int g = lane >> 2, kq = (lane & 3) * 2;
    int wm = wid & 3, wn = wid >> 2;
    int m0 = blockIdx.x * 128, n0 = blockIdx.y * 128;

    float c[2][8][4];
#pragma unroll
    for (int nt = 0; nt < 8; nt++) {
        float2 bb = *(const float2*)&bias[n0 + wn*64 + nt*8 + kq];
#pragma unroll
        for (int mt = 0; mt < 2; mt++) {
            c[mt][nt][0] = bb.x; c[mt][nt][1] = bb.y;
            c[mt][nt][2] = bb.x; c[mt][nt][3] = bb.y;
        }
    }

    for (int kc = 0; kc < K; kc += 32) {
        for (int idx = tid; idx < 1024; idx += 256) {
            int r = idx >> 3, c4 = (idx & 7) * 4;
            *(uint2*)&sAh[r*40 + c4] = *(const uint2*)&Ah[(size_t)(m0+r)*K + kc + c4];
            *(uint2*)&sBh[r*40 + c4] = *(const uint2*)&BTh[(size_t)(n0+r)*K + kc + c4];
            if (PROD3) {
                *(uint2*)&sAl[r*40 + c4] = *(const uint2*)&Al[(size_t)(m0+r)*K + kc + c4];
                *(uint2*)&sBl[r*40 + c4] = *(const uint2*)&BTl[(size_t)(n0+r)*K + kc + c4];
            }
        }
        __syncthreads();
#pragma unroll
        for (int kt = 0; kt < 2; kt++) {
            unsigned ah[2][4], al[2][4];
#pragma unroll
            for (int mt = 0; mt < 2; mt++) {
                int rb = wm*32 + mt*16;
                ah[mt][0] = *(const unsigned*)&sAh[(rb+g  )*40 + kt*16 + kq];
                ah[mt][1] = *(const unsigned*)&sAh[(rb+g+8)*40 + kt*16 + kq];
                ah[mt][2] = *(const unsigned*)&sAh[(rb+g  )*40 + kt*16 + kq + 8];
                ah[mt][3] = *(const unsigned*)&sAh[(rb+g+8)*40 + kt*16 + kq + 8];
                if (PROD3) {
                    al[mt][0] = *(const unsigned*)&sAl[(rb+g  )*40 + kt*16 + kq];
                    al[mt][1] = *(const unsigned*)&sAl[(rb+g+8)*40 + kt*16 + kq];
                    al[mt][2] = *(const unsigned*)&sAl[(rb+g  )*40 + kt*16 + kq + 8];
                    al[mt][3] = *(const unsigned*)&sAl[(rb+g+8)*40 + kt*16 + kq + 8];
                }
            }
#pragma unroll
            for (int nt = 0; nt < 8; nt++) {
                int rn = wn*64 + nt*8 + g;
                unsigned bh[2], bl[2];
                bh[0] = *(const unsigned*)&sBh[rn*40 + kt*16 + kq];
                bh[1] = *(const unsigned*)&sBh[rn*40 + kt*16 + kq + 8];
                if (PROD3) {
                    bl[0] = *(const unsigned*)&sBl[rn*40 + kt*16 + kq];
                    bl[1] = *(const unsigned*)&sBl[rn*40 + kt*16 + kq + 8];
                }
#pragma unroll
                for (int mt = 0; mt < 2; mt++) {
                    mma16816(c[mt][nt], ah[mt], bh);
                    if (PROD3) {
                        mma16816(c[mt][nt], al[mt], bh);
                        mma16816(c[mt][nt], ah[mt], bl);
                    }
                }
            }
        }
        __syncthreads();
    }

#pragma unroll
    for (int mt = 0; mt < 2; mt++) {
        int r0 = m0 + wm*32 + mt*16 + g;
#pragma unroll
        for (int nt = 0; nt < 8; nt++) {
            int col = n0 + wn*64 + nt*8 + kq;
            if (OM == 0) {
                *(float2*)&outF[(size_t)r0*D_ + col] = make_float2(c[mt][nt][0], c[mt][nt][1]);
                *(float2*)&outF[(size_t)(r0+8)*D_ + col] = make_float2(c[mt][nt][2], c[mt][nt][3]);
            } else if (OM == 1) {
                *(unsigned*)&outH[(size_t)r0*D_ + col]     = pack_bf16x2(c[mt][nt][0], c[mt][nt][1]);
                *(unsigned*)&outH[(size_t)(r0+8)*D_ + col] = pack_bf16x2(c[mt][nt][2], c[mt][nt][3]);
            } else if (OM == 2) {
                unsigned h0, l0, h1, l1;
                split2(c[mt][nt][0], c[mt][nt][1], h0, l0);
                split2(c[mt][nt][2], c[mt][nt][3], h1, l1);
                *(unsigned*)&outH[(size_t)r0*D_ + col] = h0;
                *(unsigned*)&outL[(size_t)r0*D_ + col] = l0;
                *(unsigned*)&outH[(size_t)(r0+8)*D_ + col] = h1;
                *(unsigned*)&outL[(size_t)(r0+8)*D_ + col] = l1;
            } else if (OM == 3) {
                unsigned h0, l0, h1, l1;
                split2(c[mt][nt][0], c[mt][nt][1], h0, l0);
                split2(c[mt][nt][2], c[mt][nt][3], h1, l1);
                int b0 = r0 / L_,  lA = r0 % L_;
                int b1i = (r0+8) / L_, lB = (r0+8) % L_;
                size_t t0 = ((size_t)b0*D_ + col)*L_ + lA;
                size_t t1 = ((size_t)b1i*D_ + col)*L_ + lB;
                *(unsigned short*)&outH[t0]      = (unsigned short)h0;
                *(unsigned short*)&outH[t0 + L_] = (unsigned short)(h0 >> 16);
                *(unsigned short*)&outL[t0]      = (unsigned short)l0;
                *(unsigned short*)&outL[t0 + L_] = (unsigned short)(l0 >> 16);
                *(unsigned short*)&outH[t1]      = (unsigned short)h1;
                *(unsigned short*)&outH[t1 + L_] = (unsigned short)(h1 >> 16);
                *(unsigned short*)&outL[t1]      = (unsigned short)l1;
                *(unsigned short*)&outL[t1 + L_] = (unsigned short)(l1 >> 16);
            } else {
                // single fp16, transposed
                unsigned f0 = pack_f16x2(c[mt][nt][0], c[mt][nt][1]);
                unsigned f1 = pack_f16x2(c[mt][nt][2], c[mt][nt][3]);
                int b0 = r0 / L_,  lA = r0 % L_;
                int b1i = (r0+8) / L_, lB = (r0+8) % L_;
                size_t t0 = ((size_t)b0*D_ + col)*L_ + lA;
                size_t t1 = ((size_t)b1i*D_ + col)*L_ + lB;
                outHalf[t0]      = (unsigned short)f0;
                outHalf[t0 + L_] = (unsigned short)(f0 >> 16);
                outHalf[t1]      = (unsigned short)f1;
                outHalf[t1 + L_] = (unsigned short)(f1 >> 16);
            }
        }
    }
}

// ---------------------------------------------------------------------------
// Kernel 4: flash attention, no-max softmax, fp16 2-product P.V
// ---------------------------------------------------------------------------
#define AKH 0                          // K bf16 [256][40] = 20480 B
#define AVH 20480                      // V^T fp16 [32][264] = 16896 B
#define ABI 37376                      // 256 f32
#define ASM_TOT 38400
#define KP  40
#define VP  264

__global__ void __launch_bounds__(256, 2)
attn_kernel(const float* __restrict__ ehr_times, const float* __restrict__ itv) {
    extern __shared__ char sm[];
    int tid = threadIdx.x;
    int wid = tid >> 5, lane = tid & 31;
    int g  = lane >> 2;
    int kq = (lane & 3) * 2;
    int h    = blockIdx.x;
    int half = blockIdx.y;
    int bp   = blockIdx.z;
    int b = bp >> 5;

    {
        const __nv_bfloat16* kh = g_kh + (size_t)(b*L_)*D_ + h*HD_;
        for (int idx = tid; idx < 2048; idx += 256) {
            int r = idx >> 3, c4 = (idx & 7) * 4;
            *(uint2*)(sm + AKH + r*(KP*2) + c4*2) = *(const uint2*)(kh + r*D_ + c4);
        }
    }
    {
        const unsigned short* vt = g_vt + (size_t)(b*D_ + h*HD_)*L_;
        for (int idx = tid; idx < 1024; idx += 256) {
            int hd = idx >> 5, c8 = (idx & 31) * 8;
            *(uint4*)(sm + AVH + hd*(VP*2) + c8*2) = *(const uint4*)(vt + hd*L_ + c8);
        }
    }
    {
        float s = itv[bp*2 + 0];
        float e = itv[bp*2 + 1];
        float ctr = 0.5f*(s+e);
        float t = ehr_times[b*L_ + tid];
        ((float*)(sm + ABI))[tid] = (t >= s && t <= e) ? -fabsf(t - ctr) : -1e30f;
    }

    unsigned qah[2][4];
    {
        size_t qrow = (size_t)bp*L_ + half*128 + wid*16;
#pragma unroll
        for (int kt = 0; kt < 2; kt++) {
            size_t base = (qrow + g)*D_ + h*HD_ + kt*16 + kq;
            qah[kt][0] = *(const unsigned*)(g_qh + base);
            qah[kt][1] = *(const unsigned*)(g_qh + base + 8*D_);
            qah[kt][2] = *(const unsigned*)(g_qh + base + 8);
            qah[kt][3] = *(const unsigned*)(g_qh + base + 8*D_ + 8);
        }
    }
    __syncthreads();

    const float* sb = (const float*)(sm + ABI);
    float d0 = 0.f, d1 = 0.f;
    float o[4][4];
#pragma unroll
    for (int nt = 0; nt < 4; nt++) { o[nt][0]=0.f; o[nt][1]=0.f; o[nt][2]=0.f; o[nt][3]=0.f; }

#pragma unroll 1
    for (int ch = 0; ch < 4; ch++) {
        // ---- S chunk = Q K^T (single bf16 product) ----
        float c[8][4];
#pragma unroll
        for (int nt = 0; nt < 8; nt++) { c[nt][0]=0.f; c[nt][1]=0.f; c[nt][2]=0.f; c[nt][3]=0.f; }
#pragma unroll
        for (int nt = 0; nt < 8; nt++) {
            const char* kb = sm + AKH + (ch*64 + nt*8 + g)*(KP*2);
#pragma unroll
            for (int kt = 0; kt < 2; kt++) {
                unsigned bh[2];
                bh[0] = *(const unsigned*)(kb + (kt*16 + kq)*2);
                bh[1] = *(const unsigned*)(kb + (kt*16 + kq)*2 + 16);
                mma16816(c[nt], qah[kt], bh);
            }
        }
        // ---- P = exp(s + bias), den partials ----
#pragma unroll
        for (int nt = 0; nt < 8; nt++) {
            float2 bb = *(const float2*)&sb[ch*64 + nt*8 + kq];
            c[nt][0] = __expf(c[nt][0] + bb.x);
            c[nt][1] = __expf(c[nt][1] + bb.y);
            c[nt][2] = __expf(c[nt][2] + bb.x);
            c[nt][3] = __expf(c[nt][3] + bb.y);
            d0 += c[nt][0] + c[nt][1];
            d1 += c[nt][2] + c[nt][3];
        }
        // ---- O += P_chunk * V_chunk (fp16: 2 products) ----
#pragma unroll
        for (int kt = 0; kt < 4; kt++) {
            unsigned ph[4], pl[4];
            split2h(c[2*kt][0],   c[2*kt][1],   ph[0], pl[0]);
            split2h(c[2*kt][2],   c[2*kt][3],   ph[1], pl[1]);
            split2h(c[2*kt+1][0], c[2*kt+1][1], ph[2], pl[2]);
            split2h(c[2*kt+1][2], c[2*kt+1][3], ph[3], pl[3]);
#pragma unroll
            for (int nt = 0; nt < 4; nt++) {
                const char* vb = sm + AVH + (nt*8 + g)*(VP*2) + (ch*64 + kt*16 + kq)*2;
                unsigned vv[2];
                vv[0] = *(const unsigned*)vb;
                vv[1] = *(const unsigned*)(vb + 16);
                mma16816h(o[nt], ph, vv);
                mma16816h(o[nt], pl, vv);
            }
        }
    }

    d0 += __shfl_xor_sync(0xffffffffu, d0, 1);
    d0 += __shfl_xor_sync(0xffffffffu, d0, 2);
    d1 += __shfl_xor_sync(0xffffffffu, d1, 1);
    d1 += __shfl_xor_sync(0xffffffffu, d1, 2);

    {
        float inv0 = 1.f / d0, inv1 = 1.f / d1;
        size_t orow = (size_t)bp*L_ + half*128 + wid*16;
#pragma unroll
        for (int nt = 0; nt < 4; nt++) {
            unsigned h0, l0, h1, l1;
            split2(o[nt][0]*inv0, o[nt][1]*inv0, h0, l0);
            split2(o[nt][2]*inv1, o[nt][3]*inv1, h1, l1);
            size_t i0 = (orow+g  )*D_ + h*HD_ + nt*8 + kq;
            size_t i1 = (orow+g+8)*D_ + h*HD_ + nt*8 + kq;
            *(unsigned*)&g_ctxh[i0] = h0;
            *(unsigned*)&g_ctxl[i0] = l0;
            *(unsigned*)&g_ctxh[i1] = h1;
            *(unsigned*)&g_ctxl[i1] = l1;
        }
    }
}

// ---------------------------------------------------------------------------
extern "C" void kernel_launch(void* const* d_in, const int* in_sizes, int n_in,
                              void* d_out, int out_size) {
    const float* ehr       = (const float*)d_in[0];
    const float* ehr_times = (const float*)d_in[1];
    const float* itv       = (const float*)d_in[2];
    const float* w1        = (const float*)d_in[3];
    const float* b1        = (const float*)d_in[4];
    const float* w2        = (const float*)d_in[5];
    const float* b2        = (const float*)d_in[6];
    const float* wq        = (const float*)d_in[7];
    const float* bq        = (const float*)d_in[8];
    const float* wk        = (const float*)d_in[9];
    const float* bk        = (const float*)d_in[10];
    const float* wv        = (const float*)d_in[11];
    const float* bv        = (const float*)d_in[12];
    const float* wo        = (const float*)d_in[13];
    const float* bo        = (const float*)d_in[14];
    float* out = (float*)d_out;

    __nv_bfloat16 *p_eh, *p_el, *p_kh, *p_qh;
    unsigned short *p_vt;
    __nv_bfloat16 *p_hh, *p_w2qT;
    __nv_bfloat16 *p_ctxh, *p_ctxl, *p_woTh, *p_woTl;
    __nv_bfloat16 *p_wkT, *p_wvTh, *p_wvTl;
    float *p_bq2;
    cudaGetSymbolAddress((void**)&p_eh, g_eh);
    cudaGetSymbolAddress((void**)&p_el, g_el);
    cudaGetSymbolAddress((void**)&p_kh, g_kh);
    cudaGetSymbolAddress((void**)&p_vt, g_vt);
    cudaGetSymbolAddress((void**)&p_qh, g_qh);
    cudaGetSymbolAddress((void**)&p_hh, g_hh);
    cudaGetSymbolAddress((void**)&p_w2qT, g_w2qT);
    cudaGetSymbolAddress((void**)&p_ctxh, g_ctxh);
    cudaGetSymbolAddress((void**)&p_ctxl, g_ctxl);
    cudaGetSymbolAddress((void**)&p_woTh, g_woTh);
    cudaGetSymbolAddress((void**)&p_woTl, g_woTl);
    cudaGetSymbolAddress((void**)&p_wkT, g_wkT);
    cudaGetSymbolAddress((void**)&p_wvTh, g_wvTh);
    cudaGetSymbolAddress((void**)&p_wvTl, g_wvTl);
    cudaGetSymbolAddress((void**)&p_bq2, g_bq2);

    fuse_w_kernel<<<DH_, D_>>>(w2, wq, b2, bq);
    prep_split_kernel<<<D_, D_>>>(wo, wk, wv);
    split_ehr_kernel<<<B_*L_, 256>>>(ehr);
    h_kernel<<<B_*P_*L_/32, 256>>>(ehr_times, itv, w1, b1);

    // K = ehr @ wk + bk  (single-product, single bf16 out)
    gemm_kernel<D_, false, 1><<<dim3(8, 2), 256>>>(
        p_eh, p_eh, p_wkT, p_wkT, bk, nullptr, p_kh, nullptr, nullptr);
    // V = ehr @ wv + bv  (3-product, TRANSPOSED single fp16 out)
    gemm_kernel<D_, true, 4><<<dim3(8, 2), 256>>>(
        p_eh, p_el, p_wvTh, p_wvTl, bv, nullptr, nullptr, nullptr, p_vt);
    // q = h @ W2q' + bq2'  (single-product, single bf16 out)
    gemm_kernel<DH_, false, 1><<<dim3(256, 2), 256>>>(
        p_hh, p_hh, p_w2qT, p_w2qT, p_bq2, nullptr, p_qh, nullptr, nullptr);

    cudaFuncSetAttribute(attn_kernel, cudaFuncAttributeMaxDynamicSharedMemorySize, ASM_TOT);
    attn_kernel<<<dim3(H_, 2, B_*P_), 256, ASM_TOT>>>(ehr_times, itv);

    // out = ctx @ wo + bo  (3-product, fp32 out)
    gemm_kernel<D_, true, 0><<<dim3(256, 2), 256>>>(
        p_ctxh, p_ctxl, p_woTh, p_woTl, bo, out, nullptr, nullptr, nullptr);
}